// round 17
// baseline (speedup 1.0000x reference)
#include <cuda_runtime.h>
#include <cuda_fp16.h>
#include <cstdint>

// Problem constants
#define N_TOK  8192
#define IN_F   4096
#define OUT_F  4096
#define BLK    64
#define KBLK   16
#define TM     128    // token tile per task (32x32 warp tiles)
#define LDH    72     // halves per smem row (144B stride -> conflict-free ldmatrix)
#define ABYT   (TM * LDH * 2)     // 18432
#define BBYT   (BLK * LDH * 2)    // 9216
#define BUFB   (ABYT + BBYT)      // 27648
#define SMEM_BYTES (2 * BUFB)     // 55296 (x4 CTAs = 221KB/SM)

#define NCTA   592                // 148 SMs x 4 CTAs: one exact wave
#define NTASK  4096               // 64 rb x 64 mti
#define NFULL  (NTASK - NCTA * 6) // 544 CTAs run 7 tasks, rest 6

// fp16 copies of x and w (converted each call)
__device__ __align__(16) __half g_xh[(size_t)N_TOK * IN_F];
__device__ __align__(16) __half g_wh[(size_t)BLK * KBLK * BLK * BLK];

__global__ void conv_all(const float4* __restrict__ x, const float4* __restrict__ w,
                         uint2* __restrict__ xh, uint2* __restrict__ wh,
                         int nx4, int nw4) {
    int i = blockIdx.x * blockDim.x + threadIdx.x;
    float4 v;
    uint2* o;
    if (i < nx4)            { v = x[i];       o = xh + i; }
    else if (i < nx4 + nw4) { v = w[i - nx4]; o = wh + (i - nx4); }
    else return;
    __half2 h0 = __floats2half2_rn(v.x, v.y);
    __half2 h1 = __floats2half2_rn(v.z, v.w);
    uint2 r; r.x = *(uint32_t*)&h0; r.y = *(uint32_t*)&h1;
    *o = r;
}

__device__ __forceinline__ void cp_async16(uint32_t saddr, const void* gptr) {
    asm volatile("cp.async.cg.shared.global [%0], [%1], 16;\n" :: "r"(saddr), "l"(gptr));
}
__device__ __forceinline__ void ldsm_x4(uint32_t& r0, uint32_t& r1, uint32_t& r2, uint32_t& r3,
                                        uint32_t saddr) {
    asm volatile("ldmatrix.sync.aligned.m8n8.x4.shared.b16 {%0,%1,%2,%3}, [%4];\n"
                 : "=r"(r0), "=r"(r1), "=r"(r2), "=r"(r3) : "r"(saddr));
}

__global__ __launch_bounds__(256, 4)
void bsl_f16_kernel(const float* __restrict__ bias,
                    const int*   __restrict__ col_idx,
                    float* __restrict__ out)
{
    extern __shared__ char smem[];
    const uint32_t sb0 = (uint32_t)__cvta_generic_to_shared(smem);
    const int cta = blockIdx.x;
    const int tid = threadIdx.x;
    const int lane = tid & 31;
    const int warp = tid >> 5;
    const int wm   = warp & 3;         // 4 warps along M -> 32 rows each
    const int wn   = warp >> 2;        // 2 warps along N -> 32 cols each

    const int ntask = (cta < NFULL) ? 7 : 6;
    const int NS = ntask * KBLK;       // flat stages: (task, kb)

    // ---- stage loader: stage s -> task g = cta + 592*(s>>4), kb = s&15 ----
    auto load_stage = [&](int s) {
        const int g   = cta + NCTA * (s >> 4);
        const int rb  = g & 63;
        const int m0  = (g >> 6) * TM;
        const int kb  = s & 15;
        const int lrow = tid >> 3;
        const int lchk = (tid & 7) * 8;
        const int col = __ldg(&col_idx[rb * KBLK + kb]) * BLK;
        const uint32_t so = (s & 1) * BUFB;
        const __half* xg = g_xh + (size_t)(m0 + lrow) * IN_F + col + lchk;
        const uint32_t sa = sb0 + so + (lrow * LDH + lchk) * 2;
        #pragma unroll
        for (int p = 0; p < 4; ++p)
            cp_async16(sa + p * 32 * LDH * 2, xg + (size_t)p * 32 * IN_F);
        const __half* wg = g_wh + (size_t)(rb * KBLK + kb) * (BLK * BLK) + lrow * BLK + lchk;
        const uint32_t sw = sb0 + so + ABYT + (lrow * LDH + lchk) * 2;
        #pragma unroll
        for (int p = 0; p < 2; ++p)
            cp_async16(sw + p * 32 * LDH * 2, wg + p * 32 * BLK);
        asm volatile("cp.async.commit_group;\n");
    };

    float acc[2][4][4];
    #pragma unroll
    for (int i = 0; i < 2; ++i)
        #pragma unroll
        for (int j = 0; j < 4; ++j)
            #pragma unroll
            for (int r = 0; r < 4; ++r) acc[i][j][r] = 0.f;

    load_stage(0);

    for (int s = 0; s < NS; ++s) {
        asm volatile("cp.async.wait_group 0;\n");
        __syncthreads();                       // stage s buffer ready; prior reads done

        if (s + 1 < NS)
            load_stage(s + 1);                 // overlaps compute AND epilogue below

        // fragment addresses (short live ranges)
        const uint32_t so = (s & 1) * BUFB;
        uint32_t aaddr[2], baddr[2];
        {
            const int a_row  = lane & 15;
            const int a_coff = (lane >> 4) * 8;
            const int b_row  = ((lane >> 4) << 3) + (lane & 7);
            const int b_coff = ((lane >> 3) & 1) * 8;
            #pragma unroll
            for (int i = 0; i < 2; ++i)
                aaddr[i] = sb0 + so + ((wm * 32 + i * 16 + a_row) * LDH + a_coff) * 2;
            #pragma unroll
            for (int jp = 0; jp < 2; ++jp)
                baddr[jp] = sb0 + so + ABYT + ((wn * 32 + jp * 16 + b_row) * LDH + b_coff) * 2;
        }

        #pragma unroll
        for (int ks = 0; ks < 4; ++ks) {       // K=64, 16 per MMA
            const uint32_t koff = ks * 32;     // bytes (16 halves)
            uint32_t a[2][4], b[4][2];
            #pragma unroll
            for (int i = 0; i < 2; ++i)
                ldsm_x4(a[i][0], a[i][1], a[i][2], a[i][3], aaddr[i] + koff);
            #pragma unroll
            for (int jp = 0; jp < 2; ++jp)
                ldsm_x4(b[2 * jp][0], b[2 * jp][1], b[2 * jp + 1][0], b[2 * jp + 1][1],
                        baddr[jp] + koff);
            #pragma unroll
            for (int i = 0; i < 2; ++i)
                #pragma unroll
                for (int j = 0; j < 4; ++j) {
                    asm volatile(
                        "mma.sync.aligned.m16n8k16.row.col.f32.f16.f16.f32 "
                        "{%0,%1,%2,%3}, {%4,%5,%6,%7}, {%8,%9}, {%0,%1,%2,%3};\n"
                        : "+f"(acc[i][j][0]), "+f"(acc[i][j][1]),
                          "+f"(acc[i][j][2]), "+f"(acc[i][j][3])
                        : "r"(a[i][0]), "r"(a[i][1]), "r"(a[i][2]), "r"(a[i][3]),
                          "r"(b[j][0]), "r"(b[j][1]));
                }
        }

        if ((s & 15) == 15) {                  // task done: epilogue + reset acc
            const int g  = cta + NCTA * (s >> 4);
            const int n0 = (g & 63) * BLK;
            const int m0 = (g >> 6) * TM;
            const int qr = lane >> 2, ql = lane & 3;
            #pragma unroll
            for (int j = 0; j < 4; ++j) {
                const int col = n0 + wn * 32 + j * 8 + 2 * ql;
                const float2 bv = *(const float2*)(bias + col);
                #pragma unroll
                for (int i = 0; i < 2; ++i) {
                    const int row = m0 + wm * 32 + i * 16 + qr;
                    float2 v0 = { acc[i][j][0] + bv.x, acc[i][j][1] + bv.y };
                    *(float2*)(out + (size_t)row * OUT_F + col) = v0;
                    float2 v1 = { acc[i][j][2] + bv.x, acc[i][j][3] + bv.y };
                    *(float2*)(out + (size_t)(row + 8) * OUT_F + col) = v1;
                    acc[i][j][0] = acc[i][j][1] = acc[i][j][2] = acc[i][j][3] = 0.f;
                }
            }
        }
    }
}

extern "C" void kernel_launch(void* const* d_in, const int* in_sizes, int n_in,
                              void* d_out, int out_size)
{
    const float* x       = (const float*)d_in[0];
    const float* weight  = (const float*)d_in[1];
    const float* bias    = (const float*)d_in[2];
    // d_in[3] = row_idx (deterministic repeat(arange(64),16)) — unused
    const int*   col_idx = (const int*)d_in[4];
    float* out = (float*)d_out;

    __half* xh_p; cudaGetSymbolAddress((void**)&xh_p, g_xh);
    __half* wh_p; cudaGetSymbolAddress((void**)&wh_p, g_wh);
    const int nx4 = (N_TOK * IN_F) / 4;
    const int nw4 = (BLK * KBLK * BLK * BLK) / 4;
    conv_all<<<(nx4 + nw4) / 256, 256>>>((const float4*)x, (const float4*)weight,
                                         (uint2*)xh_p, (uint2*)wh_p, nx4, nw4);

    cudaFuncSetAttribute(bsl_f16_kernel,
                         cudaFuncAttributeMaxDynamicSharedMemorySize, SMEM_BYTES);
    bsl_f16_kernel<<<NCTA, 256, SMEM_BYTES>>>(bias, col_idx, out);  // persistent, 1 wave
}